// round 8
// baseline (speedup 1.0000x reference)
#include <cuda_runtime.h>
#include <cstdint>

#define NC      19
#define HW      (512 * 512)
#define NB      8
#define GX      64                  // blocks per image -> 512 blocks (~3.5/SM, one wave)
#define PXB     (HW / GX)           // 4096 pixels per block (exact)
#define THREADS 320
#define NWARP   10
#define NBINS   (NC * NC + NC)      // 380
#define NBLK    (NB * GX)           // 512

// Dynamic smem layout (floats):
//   acc [NC][NC][32] : 11552 floats   bin (c,k), lane-private column
//   cnt [NC][32]     :   608 floats
//   labels u8[PXB]   :  1024 u32 words
#define CNT_OFF  (NC * NC * 32)
#define LAB_OFF  (CNT_OFF + NC * 32)
#define SMEM_FLOATS (LAB_OFF + PXB / 4)          // 13184 floats = 52,736 B

// Per-block partials, transposed for coalesced float4 reads in finalize.
__device__ __align__(16) float g_part[NB][NBINS][GX];
__device__ unsigned int g_count;                  // zero-init; reset by finalizer

// Accumulate one channel job. Chain-free: atomicAdd has no return value, so
// there is no LDS->FADD->STS dependency chain; each cell (c,k,lane) is touched
// by exactly ONE thread -> no contention, deterministic order.
__device__ __forceinline__ void accum_channel(const float4* __restrict__ sp,
                                              const unsigned* __restrict__ labw,
                                              float* __restrict__ accc, int lane) {
#pragma unroll 4
    for (int j = 0; j < PXB / 128; j++) {         // 32 iterations
        const int idx = j * 32 + lane;
        float4 v = __ldcs(sp + idx);              // 512B/warp contiguous
        unsigned pk = labw[idx];                  // conflict-free u32 read
        atomicAdd(accc + (pk & 0xffu) * 32,         v.x);
        atomicAdd(accc + ((pk >> 8) & 0xffu) * 32,  v.y);
        atomicAdd(accc + ((pk >> 16) & 0xffu) * 32, v.z);
        atomicAdd(accc + (pk >> 24) * 32,           v.w);
    }
}

__global__ __launch_bounds__(THREADS, 4)
void fused_kernel(const float* __restrict__ seg, const void* __restrict__ lab,
                  float* __restrict__ out) {
    extern __shared__ float sm[];
    float* acc = sm;
    float* cnt = sm + CNT_OFF;
    unsigned int* labw = (unsigned int*)(sm + LAB_OFF);

    const int tid  = threadIdx.x;
    const int lane = tid & 31;
    const int w    = tid >> 5;
    const int gx   = blockIdx.x;
    const int b    = blockIdx.y;

    // Zero accumulators (labels fully overwritten below).
    for (int i = tid; i < LAB_OFF; i += THREADS) sm[i] = 0.0f;

    // Label dtype detect: odd 32-bit words of the first 32 labels all zero <=> int64.
    int oddv = ((const int*)lab)[2 * lane + 1];
    bool is64 = (__ballot_sync(0xffffffffu, oddv != 0) == 0u);

    const long long pbase = (long long)b * HW + (long long)gx * PXB;

    // Stage labels for this block's 4096 pixels as packed u8 (4 per u32).
    if (is64) {
        const longlong2* L = (const longlong2*)((const long long*)lab + pbase);
        for (int wd = tid; wd < PXB / 4; wd += THREADS) {
            longlong2 a = __ldcs(L + 2 * wd);
            longlong2 c = __ldcs(L + 2 * wd + 1);
            labw[wd] = (unsigned)a.x | ((unsigned)a.y << 8) |
                       ((unsigned)c.x << 16) | ((unsigned)c.y << 24);
        }
    } else {
        const int4* L = (const int4*)((const int*)lab + pbase);
        for (int wd = tid; wd < PXB / 4; wd += THREADS) {
            int4 a = __ldcs(L + wd);
            labw[wd] = (unsigned)a.x | ((unsigned)a.y << 8) |
                       ((unsigned)a.z << 16) | ((unsigned)a.w << 24);
        }
    }
    __syncthreads();

    // Jobs: 0..18 = channels, 19 = counts. Warp w gets jobs {w, w+10}.
    const float* segb = seg + (size_t)b * NC * HW + (size_t)gx * PXB;
    {
        const int c = w;                          // job 1: channel w (0..9)
        accum_channel((const float4*)(segb + (size_t)c * HW),
                      labw, acc + c * (NC * 32) + lane, lane);
    }
    if (w + 10 < NC) {                            // job 2: channel 10..18
        const int c = w + 10;
        accum_channel((const float4*)(segb + (size_t)c * HW),
                      labw, acc + c * (NC * 32) + lane, lane);
    } else {                                      // warp 9: counts
        float* cl = cnt + lane;
#pragma unroll 4
        for (int j = 0; j < PXB / 128; j++) {
            unsigned pk = labw[j * 32 + lane];
            atomicAdd(cl + (pk & 0xffu) * 32,         1.0f);
            atomicAdd(cl + ((pk >> 8) & 0xffu) * 32,  1.0f);
            atomicAdd(cl + ((pk >> 16) & 0xffu) * 32, 1.0f);
            atomicAdd(cl + (pk >> 24) * 32,           1.0f);
        }
    }
    __syncthreads();

    // Reduce 32 lane-columns per bin (rotation keeps intra-warp conflict-free).
    for (int bin = tid; bin < NBINS; bin += THREADS) {
        const float* col = sm + bin * 32;         // acc and cnt are contiguous
        float s = 0.0f;
#pragma unroll
        for (int j = 0; j < 32; j++) s += col[(j + tid) & 31];
        g_part[b][bin][gx] = s;
    }

    // Last-block finalize handshake.
    __threadfence();
    __syncthreads();
    __shared__ unsigned int s_last;
    if (tid == 0) s_last = atomicAdd(&g_count, 1u);
    __syncthreads();
    if (s_last != NBLK - 1) return;
    __threadfence();

    // ---- Finalize (last block, 320 threads) ----
    float* sS = sm;   // reuse dynamic smem: [NB*NBINS] floats (3040 <= 13184)
    const float4* gp4 = (const float4*)&g_part[0][0][0];
    for (int pair = tid; pair < NB * NBINS; pair += THREADS) {
        float s = 0.0f;
#pragma unroll
        for (int j = 0; j < GX / 4; j++) {        // 16 independent LDG.128
            float4 v = __ldcg(gp4 + pair * (GX / 4) + j);
            s += (v.x + v.y) + (v.z + v.w);
        }
        sS[pair] = s;
    }
    __syncthreads();

    double local = 0.0;
    for (int t2 = tid; t2 < NC * NC; t2 += THREADS) {
        const int i = t2 / NC, k = t2 % NC;
#pragma unroll
        for (int bb = 0; bb < NB; bb++) {
            const float* r = sS + bb * NBINS;
            float ci_ = r[NC * NC + i], ck = r[NC * NC + k];
            float Sii = r[i * NC + i],  Sik = r[i * NC + k];
            double alpha = (ci_ > 0.0f) ? (double)Sii / (double)ci_ : 0.0;
            double beta  = (ck  > 0.0f) ? 1.0 - (double)Sik / (double)ck : 0.0;
            local += log(0.5 * (alpha + beta + 2.220446049250313e-16));
        }
    }
#pragma unroll
    for (int o = 16; o; o >>= 1)
        local += __shfl_down_sync(0xffffffffu, local, o);
    __shared__ double ws[NWARP];
    if (lane == 0) ws[w] = local;
    __syncthreads();
    if (tid == 0) {
        double tot = 0.0;
#pragma unroll
        for (int j = 0; j < NWARP; j++) tot += ws[j];
        out[0] = (float)(-0.5 * tot / (double)NB);
        g_count = 0u;                             // reset for next graph replay
    }
}

extern "C" void kernel_launch(void* const* d_in, const int* in_sizes, int n_in,
                              void* d_out, int out_size) {
    const float* seg = (const float*)d_in[0];
    const void*  lab = d_in[1];
    float* out = (float*)d_out;

    const int smem = SMEM_FLOATS * sizeof(float);   // 52,736 B
    (void)cudaFuncSetAttribute(fused_kernel,
                               cudaFuncAttributeMaxDynamicSharedMemorySize, smem);

    dim3 grid(GX, NB);
    fused_kernel<<<grid, THREADS, smem>>>(seg, lab, out);
}

// round 9
// speedup vs baseline: 1.4858x; 1.4858x over previous
#include <cuda_runtime.h>
#include <cstdint>

#define NC      19
#define HW      (512 * 512)
#define NB      8
#define GX      32                  // 256 blocks -> one wave at occupancy 2
#define PXB     (HW / GX)           // 8192 pixels per block (exact)
#define THREADS 320
#define NWARP   10
#define NBINS   (NC * NC + NC)      // 380
#define NBLK    (NB * GX)           // 256
#define NST     16                  // stages per channel: 8192 px / 512 px-per-stage

// Dynamic smem layout (float units):
//   acc [NC][NC][32] : 11552   lane-private bin columns (bank == lane)
//   cnt [NC][32]     :   608
//   labw u8[PXB]     :  2048 u32 words
//   buf [NWARP][256] float4 : 10240 floats (depth-2 cp.async staging, 4KB/warp)
#define CNT_OFF  (NC * NC * 32)
#define LAB_OFF  (CNT_OFF + NC * 32)
#define BUF_OFF  (LAB_OFF + PXB / 4)
#define SMEM_FLOATS (BUF_OFF + NWARP * 256 * 4)   // 24448 floats = 97,792 B

__device__ __align__(16) float g_part[NB][NBINS][GX];
__device__ unsigned int g_count;                  // zero-init; reset by finalizer

__device__ __forceinline__ void cpasync16(uint32_t dst, const void* src) {
    asm volatile("cp.async.cg.shared.global [%0], [%1], 16;" :: "r"(dst), "l"(src) : "memory");
}
__device__ __forceinline__ void cpcommit() {
    asm volatile("cp.async.commit_group;" ::: "memory");
}
__device__ __forceinline__ void cpwait1() {
    asm volatile("cp.async.wait_group 1;" ::: "memory");
}
__device__ __forceinline__ void cpwait0() {
    asm volatile("cp.async.wait_group 0;" ::: "memory");
}

// One channel (8192 px) through a per-warp depth-2 cp.async pipeline.
// Stage s = 128 float4 (512 px); lane handles 4 float4 at slots i*32+lane
// (writes and reads ONLY its own slots -> per-thread wait_group suffices,
//  no warp/block sync in the mainloop). Staging layout is coalesced
// (stride 16B across lanes) -> conflict-free LDS.128.
__device__ __forceinline__ void accum_channel(const float4* __restrict__ g4,
                                              const unsigned* __restrict__ labw,
                                              float* __restrict__ accc,
                                              float4* __restrict__ bufw,
                                              uint32_t bufaddr, int lane) {
    // prologue: stages 0,1
#pragma unroll
    for (int s = 0; s < 2; s++) {
        uint32_t dst = bufaddr + (unsigned)((s & 1) * 128 + lane) * 16u;
        const float4* src = g4 + s * 128 + lane;
#pragma unroll
        for (int i = 0; i < 4; i++) cpasync16(dst + i * 512u, src + i * 32);
        cpcommit();
    }
    for (int s = 0; s < NST; s++) {
        if (s == NST - 1) cpwait0(); else cpwait1();   // stage s landed
        const int half = (s & 1) * 128;
#pragma unroll
        for (int i = 0; i < 4; i++) {
            float4 v = bufw[half + i * 32 + lane];      // LDS.128, conflict-free
            unsigned pk = labw[s * 128 + i * 32 + lane];
            accc[(pk & 0xffu) * 32]         += v.x;     // LDS/FADD/STS, bank==lane
            accc[((pk >> 8) & 0xffu) * 32]  += v.y;
            accc[((pk >> 16) & 0xffu) * 32] += v.z;
            accc[(pk >> 24) * 32]           += v.w;
        }
        if (s + 2 < NST) {                              // refill this half
            uint32_t dst = bufaddr + (unsigned)(half + lane) * 16u;
            const float4* src = g4 + (s + 2) * 128 + lane;
#pragma unroll
            for (int i = 0; i < 4; i++) cpasync16(dst + i * 512u, src + i * 32);
            cpcommit();
        }
    }
}

__global__ __launch_bounds__(THREADS, 2)
void fused_kernel(const float* __restrict__ seg, const void* __restrict__ lab,
                  float* __restrict__ out) {
    extern __shared__ float sm[];
    float* acc = sm;
    float* cnt = sm + CNT_OFF;
    unsigned int* labw = (unsigned int*)(sm + LAB_OFF);

    const int tid  = threadIdx.x;
    const int lane = tid & 31;
    const int w    = tid >> 5;
    const int gx   = blockIdx.x;
    const int b    = blockIdx.y;

    float4* bufw = (float4*)(sm + BUF_OFF) + w * 256;
    const uint32_t bufaddr = (uint32_t)__cvta_generic_to_shared(bufw);

    // Zero accumulators (labels and buf fully overwritten).
    for (int i = tid; i < LAB_OFF; i += THREADS) sm[i] = 0.0f;

    // Label dtype: odd 32-bit words of first 32 labels all zero <=> int64.
    int oddv = ((const int*)lab)[2 * lane + 1];
    bool is64 = (__ballot_sync(0xffffffffu, oddv != 0) == 0u);

    const long long pbase = (long long)b * HW + (long long)gx * PXB;

    // Stage labels as packed u8 (4 per u32).
    if (is64) {
        const longlong2* L = (const longlong2*)((const long long*)lab + pbase);
        for (int wd = tid; wd < PXB / 4; wd += THREADS) {
            longlong2 a = __ldcs(L + 2 * wd);
            longlong2 c = __ldcs(L + 2 * wd + 1);
            labw[wd] = (unsigned)a.x | ((unsigned)a.y << 8) |
                       ((unsigned)c.x << 16) | ((unsigned)c.y << 24);
        }
    } else {
        const int4* L = (const int4*)((const int*)lab + pbase);
        for (int wd = tid; wd < PXB / 4; wd += THREADS) {
            int4 a = __ldcs(L + wd);
            labw[wd] = (unsigned)a.x | ((unsigned)a.y << 8) |
                       ((unsigned)a.z << 16) | ((unsigned)a.w << 24);
        }
    }
    __syncthreads();

    // Jobs: warp w -> channel w; then channel w+10 (w<9) or counts (w==9).
    const float* segb = seg + (size_t)b * NC * HW + (size_t)gx * PXB;
    accum_channel((const float4*)(segb + (size_t)w * HW), labw,
                  acc + w * (NC * 32) + lane, bufw, bufaddr, lane);
    if (w + 10 < NC) {
        const int c = w + 10;
        accum_channel((const float4*)(segb + (size_t)c * HW), labw,
                      acc + c * (NC * 32) + lane, bufw, bufaddr, lane);
    } else {
        float* cl = cnt + lane;
#pragma unroll 4
        for (int j = 0; j < PXB / 128; j++) {
            unsigned pk = labw[j * 32 + lane];
            cl[(pk & 0xffu) * 32]         += 1.0f;
            cl[((pk >> 8) & 0xffu) * 32]  += 1.0f;
            cl[((pk >> 16) & 0xffu) * 32] += 1.0f;
            cl[(pk >> 24) * 32]           += 1.0f;
        }
    }
    __syncthreads();

    // Reduce 32 lane columns per bin (rotation stays conflict-free).
    for (int bin = tid; bin < NBINS; bin += THREADS) {
        const float* col = sm + bin * 32;          // acc and cnt contiguous
        float s = 0.0f;
#pragma unroll
        for (int j = 0; j < 32; j++) s += col[(j + tid) & 31];
        g_part[b][bin][gx] = s;
    }

    // Last-block finalize handshake.
    __threadfence();
    __syncthreads();
    __shared__ unsigned int s_last;
    if (tid == 0) s_last = atomicAdd(&g_count, 1u);
    __syncthreads();
    if (s_last != NBLK - 1) return;
    __threadfence();

    // ---- Finalize (last block) ----
    float* sS = sm;   // reuse: [NB*NBINS] floats
    const float4* gp4 = (const float4*)&g_part[0][0][0];
    for (int pair = tid; pair < NB * NBINS; pair += THREADS) {
        float s = 0.0f;
#pragma unroll
        for (int j = 0; j < GX / 4; j++) {         // 8 independent LDG.128
            float4 v = __ldcg(gp4 + pair * (GX / 4) + j);
            s += (v.x + v.y) + (v.z + v.w);
        }
        sS[pair] = s;
    }
    __syncthreads();

    double local = 0.0;
    for (int t2 = tid; t2 < NC * NC; t2 += THREADS) {
        const int i = t2 / NC, k = t2 % NC;
#pragma unroll
        for (int bb = 0; bb < NB; bb++) {
            const float* r = sS + bb * NBINS;
            float ci_ = r[NC * NC + i], ck = r[NC * NC + k];
            float Sii = r[i * NC + i],  Sik = r[i * NC + k];
            double alpha = (ci_ > 0.0f) ? (double)Sii / (double)ci_ : 0.0;
            double beta  = (ck  > 0.0f) ? 1.0 - (double)Sik / (double)ck : 0.0;
            local += log(0.5 * (alpha + beta + 2.220446049250313e-16));
        }
    }
#pragma unroll
    for (int o = 16; o; o >>= 1)
        local += __shfl_down_sync(0xffffffffu, local, o);
    __shared__ double ws[NWARP];
    if (lane == 0) ws[w] = local;
    __syncthreads();
    if (tid == 0) {
        double tot = 0.0;
#pragma unroll
        for (int j = 0; j < NWARP; j++) tot += ws[j];
        out[0] = (float)(-0.5 * tot / (double)NB);
        g_count = 0u;                              // reset for next graph replay
    }
}

extern "C" void kernel_launch(void* const* d_in, const int* in_sizes, int n_in,
                              void* d_out, int out_size) {
    const float* seg = (const float*)d_in[0];
    const void*  lab = d_in[1];
    float* out = (float*)d_out;

    const int smem = SMEM_FLOATS * sizeof(float);   // 97,792 B
    (void)cudaFuncSetAttribute(fused_kernel,
                               cudaFuncAttributeMaxDynamicSharedMemorySize, smem);

    dim3 grid(GX, NB);
    fused_kernel<<<grid, THREADS, smem>>>(seg, lab, out);
}